// round 9
// baseline (speedup 1.0000x reference)
#include <cuda_runtime.h>
#include <math.h>

#define NHEADS 8
#define EMB    64
#define FA     256
#define FB     256
#define BATCH  2
#define SEQ    2048
#define HFB    (NHEADS*FB)   // 2048

// ---------------- scratch (device globals; no allocations allowed) ----------
__device__ float g_q[(size_t)BATCH*NHEADS*EMB*SEQ];          // [b][h*64+e][n]  8MB
__device__ float g_k[(size_t)BATCH*NHEADS*EMB*SEQ];          // 8MB
__device__ float g_pre[(size_t)BATCH*NHEADS*SEQ*SEQ];        // [bh][q][k] 256MB (pre -> coeff in place)
__device__ float g_feat[(size_t)BATCH*SEQ*HFB];              // [b][q][h*256+f] 32MB

// ---------------- common SGEMM tile config ----------------------------------
#define BM 128
#define BN 128
#define BK 8
#define TM 8
#define TN 8
// 256 threads per block, each computes 8x8

// ---------------- tiny init --------------------------------------------------
__global__ void zero_l1_kernel(float* l1) {
    if (threadIdx.x < BATCH) l1[threadIdx.x] = 0.0f;
}

// ---------------- kernel 1: q/k embedding GEMMs ------------------------------
// C[o][n] = sum_f W[o][f] * Z[b][f][n]; M=512, N=2048, K=256
// grid: (SEQ/BN=16, 512/BM=4, 4)  z: b=z>>1, sel=z&1
__global__ __launch_bounds__(256) void embed_kernel(
    const float* __restrict__ Wa, const float* __restrict__ za,
    const float* __restrict__ Wb, const float* __restrict__ zb)
{
    const int bz = blockIdx.z;
    const int b = bz >> 1, sel = bz & 1;
    const float* __restrict__ A  = sel ? Wb : Wa;                       // [512 x 256] row-major
    const float* __restrict__ Bm = (sel ? zb : za) + (size_t)b*FA*SEQ;  // [256 x 2048] row-major
    float* __restrict__ C = (sel ? g_k : g_q) + (size_t)b*(NHEADS*EMB)*SEQ;

    __shared__ float As[BK][BM];
    __shared__ float Bs[BK][BN];

    const int tid = threadIdx.x;
    const int m0 = blockIdx.y * BM;
    const int n0 = blockIdx.x * BN;
    const int K = FA;
    const int ty = tid >> 4, tx = tid & 15;

    float acc[TM][TN] = {};

    for (int k0 = 0; k0 < K; k0 += BK) {
        // A transposed load: [M,K] row-major -> As[kk][mm]
        {
            const int mm = tid >> 1, kk = (tid & 1) * 4;
            float4 v = *(const float4*)&A[(size_t)(m0 + mm) * K + k0 + kk];
            As[kk + 0][mm] = v.x; As[kk + 1][mm] = v.y;
            As[kk + 2][mm] = v.z; As[kk + 3][mm] = v.w;
        }
        // B direct load: [K,N] row-major -> Bs[kk][nn]
        {
            const int kk = tid >> 5, nn = (tid & 31) * 4;
            *(float4*)&Bs[kk][nn] = *(const float4*)&Bm[(size_t)(k0 + kk) * SEQ + n0 + nn];
        }
        __syncthreads();
        #pragma unroll
        for (int kk = 0; kk < BK; kk++) {
            float a[TM], bb[TN];
            *(float4*)&a[0]  = *(const float4*)&As[kk][ty * TM];
            *(float4*)&a[4]  = *(const float4*)&As[kk][ty * TM + 4];
            *(float4*)&bb[0] = *(const float4*)&Bs[kk][tx * TN];
            *(float4*)&bb[4] = *(const float4*)&Bs[kk][tx * TN + 4];
            #pragma unroll
            for (int i = 0; i < TM; i++)
                #pragma unroll
                for (int j = 0; j < TN; j++)
                    acc[i][j] += a[i] * bb[j];
        }
        __syncthreads();
    }
    #pragma unroll
    for (int i = 0; i < TM; i++) {
        float* crow = &C[(size_t)(m0 + ty * TM + i) * SEQ + n0 + tx * TN];
        *(float4*)&crow[0] = make_float4(acc[i][0], acc[i][1], acc[i][2], acc[i][3]);
        *(float4*)&crow[4] = make_float4(acc[i][4], acc[i][5], acc[i][6], acc[i][7]);
    }
}

// ---------------- kernel 2: pre = 0.125 * q^T k  + |pre| accumulation --------
// A = q[b,h]: [64 x 2048] (e-major rows), B = k[b,h] same. C[qi][ki], M=N=2048, K=64.
// grid: (16, 16, 16)
__global__ __launch_bounds__(256) void pre_kernel(float* __restrict__ l1)
{
    const int bh = blockIdx.z;
    const int b = bh >> 3;
    const float* __restrict__ A  = g_q + (size_t)bh * EMB * SEQ;
    const float* __restrict__ Bm = g_k + (size_t)bh * EMB * SEQ;
    float* __restrict__ C = g_pre + (size_t)bh * SEQ * SEQ;

    __shared__ float As[BK][BM];
    __shared__ float Bs[BK][BN];
    __shared__ float red[256];

    const int tid = threadIdx.x;
    const int m0 = blockIdx.y * BM;
    const int n0 = blockIdx.x * BN;
    const int ty = tid >> 4, tx = tid & 15;

    float acc[TM][TN] = {};

    for (int k0 = 0; k0 < EMB; k0 += BK) {
        const int kk = tid >> 5, cc = (tid & 31) * 4;
        *(float4*)&As[kk][cc] = *(const float4*)&A [(size_t)(k0 + kk) * SEQ + m0 + cc];
        *(float4*)&Bs[kk][cc] = *(const float4*)&Bm[(size_t)(k0 + kk) * SEQ + n0 + cc];
        __syncthreads();
        #pragma unroll
        for (int k = 0; k < BK; k++) {
            float a[TM], bb[TN];
            *(float4*)&a[0]  = *(const float4*)&As[k][ty * TM];
            *(float4*)&a[4]  = *(const float4*)&As[k][ty * TM + 4];
            *(float4*)&bb[0] = *(const float4*)&Bs[k][tx * TN];
            *(float4*)&bb[4] = *(const float4*)&Bs[k][tx * TN + 4];
            #pragma unroll
            for (int i = 0; i < TM; i++)
                #pragma unroll
                for (int j = 0; j < TN; j++)
                    acc[i][j] += a[i] * bb[j];
        }
        __syncthreads();
    }

    float asum = 0.0f;
    #pragma unroll
    for (int i = 0; i < TM; i++) {
        float4 v0, v1;
        float vv[8];
        #pragma unroll
        for (int j = 0; j < TN; j++) {
            float v = acc[i][j] * 0.125f;
            vv[j] = v;
            asum += fabsf(v);
        }
        v0 = make_float4(vv[0], vv[1], vv[2], vv[3]);
        v1 = make_float4(vv[4], vv[5], vv[6], vv[7]);
        float* crow = &C[(size_t)(m0 + ty * TM + i) * SEQ + n0 + tx * TN];
        *(float4*)&crow[0] = v0;
        *(float4*)&crow[4] = v1;
    }

    // block-reduce |pre| and one atomic per block
    red[tid] = asum;
    __syncthreads();
    for (int s = 128; s > 0; s >>= 1) {
        if (tid < s) red[tid] += red[tid + s];
        __syncthreads();
    }
    if (tid == 0) {
        const float inv = 1.0f / ((float)NHEADS * (float)SEQ * (float)SEQ);
        atomicAdd(&l1[b], red[0] * inv);
    }
}

// ---------------- kernel 3: row softmax over keys (in place) -----------------
// grid: (SEQ, BATCH*NHEADS), 256 threads, 8 elems/thread
__global__ __launch_bounds__(256) void softmax_kernel()
{
    const int q  = blockIdx.x;
    const int bh = blockIdx.y;
    float* __restrict__ p = g_pre + ((size_t)bh * SEQ + q) * SEQ;
    const int tid = threadIdx.x;

    __shared__ float sm[256];

    float vals[8];
    float m = -1e30f;
    #pragma unroll
    for (int i = 0; i < 8; i++) {
        vals[i] = p[tid + i * 256];
        m = fmaxf(m, vals[i]);
    }
    sm[tid] = m; __syncthreads();
    for (int s = 128; s > 0; s >>= 1) {
        if (tid < s) sm[tid] = fmaxf(sm[tid], sm[tid + s]);
        __syncthreads();
    }
    m = sm[0];
    __syncthreads();

    float sum = 0.0f;
    #pragma unroll
    for (int i = 0; i < 8; i++) {
        vals[i] = __expf(vals[i] - m);
        sum += vals[i];
    }
    sm[tid] = sum; __syncthreads();
    for (int s = 128; s > 0; s >>= 1) {
        if (tid < s) sm[tid] += sm[tid + s];
        __syncthreads();
    }
    const float inv = 1.0f / sm[0];
    #pragma unroll
    for (int i = 0; i < 8; i++)
        p[tid + i * 256] = vals[i] * inv;
}

// ---------------- shared SGEMM helper: A [M,K] row-major, B [N,K] row-major --
// C[m][n] = sum_k A[m][k] * B[n][k]
__device__ __forceinline__ void sgemm_mk_nk(
    const float* __restrict__ A, int lda,
    const float* __restrict__ B, int ldb,
    float* __restrict__ C, int ldc, int K)
{
    __shared__ float As[BK][BM];
    __shared__ float Bs[BK][BN];

    const int tid = threadIdx.x;
    const int m0 = blockIdx.y * BM;
    const int n0 = blockIdx.x * BN;
    const int ty = tid >> 4, tx = tid & 15;
    const int lr = tid >> 1, lk = (tid & 1) * 4;

    float acc[TM][TN] = {};

    for (int k0 = 0; k0 < K; k0 += BK) {
        float4 va = *(const float4*)&A[(size_t)(m0 + lr) * lda + k0 + lk];
        float4 vb = *(const float4*)&B[(size_t)(n0 + lr) * ldb + k0 + lk];
        As[lk + 0][lr] = va.x; As[lk + 1][lr] = va.y;
        As[lk + 2][lr] = va.z; As[lk + 3][lr] = va.w;
        Bs[lk + 0][lr] = vb.x; Bs[lk + 1][lr] = vb.y;
        Bs[lk + 2][lr] = vb.z; Bs[lk + 3][lr] = vb.w;
        __syncthreads();
        #pragma unroll
        for (int kk = 0; kk < BK; kk++) {
            float a[TM], bb[TN];
            *(float4*)&a[0]  = *(const float4*)&As[kk][ty * TM];
            *(float4*)&a[4]  = *(const float4*)&As[kk][ty * TM + 4];
            *(float4*)&bb[0] = *(const float4*)&Bs[kk][tx * TN];
            *(float4*)&bb[4] = *(const float4*)&Bs[kk][tx * TN + 4];
            #pragma unroll
            for (int i = 0; i < TM; i++)
                #pragma unroll
                for (int j = 0; j < TN; j++)
                    acc[i][j] += a[i] * bb[j];
        }
        __syncthreads();
    }
    #pragma unroll
    for (int i = 0; i < TM; i++) {
        float* crow = &C[(size_t)(m0 + ty * TM + i) * ldc + n0 + tx * TN];
        *(float4*)&crow[0] = make_float4(acc[i][0], acc[i][1], acc[i][2], acc[i][3]);
        *(float4*)&crow[4] = make_float4(acc[i][4], acc[i][5], acc[i][6], acc[i][7]);
    }
}

// ---------------- kernel 4: feat = coeff @ v^T  ------------------------------
// per (b,h): M=2048, N=256, K=2048.  grid: (2, 16, 16)
__global__ __launch_bounds__(256) void feat_kernel(const float* __restrict__ zb)
{
    const int bh = blockIdx.z;
    const int b = bh >> 3, h = bh & 7;
    sgemm_mk_nk(g_pre + (size_t)bh * SEQ * SEQ, SEQ,
                zb + (size_t)b * FB * SEQ, SEQ,
                g_feat + (size_t)b * SEQ * HFB + h * FB, HFB, SEQ);
}

// ---------------- kernel 5: out = Feat @ W_c^T -------------------------------
// per b: M=2048, N=256, K=2048.  grid: (2, 16, 2)
__global__ __launch_bounds__(256) void out_kernel(const float* __restrict__ Wc,
                                                  float* __restrict__ out)
{
    const int b = blockIdx.z;
    sgemm_mk_nk(g_feat + (size_t)b * SEQ * HFB, HFB,
                Wc, HFB,
                out + (size_t)b * SEQ * FA, FA, HFB);
}

// ---------------- launch -----------------------------------------------------
extern "C" void kernel_launch(void* const* d_in, const int* in_sizes, int n_in,
                              void* d_out, int out_size)
{
    const float* z_a = (const float*)d_in[0];   // [2, 256, 2048]
    const float* z_b = (const float*)d_in[1];   // [2, 256, 2048]
    const float* W_a = (const float*)d_in[2];   // [512, 256]
    const float* W_b = (const float*)d_in[3];   // [512, 256]
    const float* W_c = (const float*)d_in[4];   // [256, 2048]
    float* out = (float*)d_out;                 // [2, 2048, 256] then l1 [2]
    float* l1  = out + (size_t)BATCH * SEQ * FA;

    zero_l1_kernel<<<1, 32>>>(l1);

    {
        dim3 grid(SEQ / BN, (NHEADS * EMB) / BM, BATCH * 2);
        embed_kernel<<<grid, 256>>>(W_a, z_a, W_b, z_b);
    }
    {
        dim3 grid(SEQ / BN, SEQ / BM, BATCH * NHEADS);
        pre_kernel<<<grid, 256>>>(l1);
    }
    {
        dim3 grid(SEQ, BATCH * NHEADS);
        softmax_kernel<<<grid, 256>>>();
    }
    {
        dim3 grid(FB / BN, SEQ / BM, BATCH * NHEADS);
        feat_kernel<<<grid, 256>>>(z_b);
    }
    {
        dim3 grid(FA / BN, SEQ / BM, BATCH);
        out_kernel<<<grid, 256>>>(W_c, out);
    }
}

// round 11
// speedup vs baseline: 2.3229x; 2.3229x over previous
#include <cuda_runtime.h>
#include <cuda_bf16.h>
#include <math.h>
#include <stdint.h>

#define NHEADS 8
#define EMB    64
#define FA     256
#define FB     256
#define BATCH  2
#define SEQ    2048
#define HFB    (NHEADS*FB)   // 2048

// ---------------- scratch (device globals; no allocations allowed) ----------
__device__ float g_pre[(size_t)BATCH*NHEADS*SEQ*SEQ];            // 256MB fp32 logits
// qT/kT: [bh][n][e] bf16 hi/lo
__device__ __nv_bfloat16 g_qh[(size_t)BATCH*NHEADS*SEQ*EMB];
__device__ __nv_bfloat16 g_ql[(size_t)BATCH*NHEADS*SEQ*EMB];
__device__ __nv_bfloat16 g_kh[(size_t)BATCH*NHEADS*SEQ*EMB];
__device__ __nv_bfloat16 g_kl[(size_t)BATCH*NHEADS*SEQ*EMB];
// coeff: [bh][q][k] bf16 hi/lo (written by softmax)
__device__ __nv_bfloat16 g_ch[(size_t)BATCH*NHEADS*SEQ*SEQ];
__device__ __nv_bfloat16 g_cl[(size_t)BATCH*NHEADS*SEQ*SEQ];
// v = z_b: [b][f][k] bf16 hi/lo ; Wc: [o][k] bf16 hi/lo
__device__ __nv_bfloat16 g_vh[(size_t)BATCH*FB*SEQ];
__device__ __nv_bfloat16 g_vl[(size_t)BATCH*FB*SEQ];
__device__ __nv_bfloat16 g_wh[(size_t)FA*HFB];
__device__ __nv_bfloat16 g_wl[(size_t)FA*HFB];
// feat: [b][q][hf] bf16 hi/lo
__device__ __nv_bfloat16 g_fh[(size_t)BATCH*SEQ*HFB];
__device__ __nv_bfloat16 g_fl[(size_t)BATCH*SEQ*HFB];

// ============================ helpers ========================================
__device__ __forceinline__ uint32_t smem_u32(const void* p) {
    uint32_t a;
    asm("{ .reg .u64 t; cvta.to.shared.u64 t, %1; cvt.u32.u64 %0, t; }" : "=r"(a) : "l"(p));
    return a;
}
#define CP_ASYNC16(dst, src) \
    asm volatile("cp.async.cg.shared.global [%0], [%1], 16;" :: "r"(dst), "l"(src))
#define CP_COMMIT() asm volatile("cp.async.commit_group;" ::: "memory")
#define CP_WAIT(n)  asm volatile("cp.async.wait_group %0;" :: "n"(n) : "memory")

#define LDSM4(r, addr) \
    asm volatile("ldmatrix.sync.aligned.m8n8.x4.shared.b16 {%0,%1,%2,%3}, [%4];" \
        : "=r"((r)[0]), "=r"((r)[1]), "=r"((r)[2]), "=r"((r)[3]) : "r"(addr))

#define MMA16816(d, a, b0, b1)                                                  \
    asm volatile("mma.sync.aligned.m16n8k16.row.col.f32.bf16.bf16.f32 "         \
        "{%0,%1,%2,%3}, {%4,%5,%6,%7}, {%8,%9}, {%0,%1,%2,%3};"                 \
        : "+f"((d)[0]), "+f"((d)[1]), "+f"((d)[2]), "+f"((d)[3])                \
        : "r"((a)[0]), "r"((a)[1]), "r"((a)[2]), "r"((a)[3]), "r"(b0), "r"(b1))

__device__ __forceinline__ void cvt_hl(float v, __nv_bfloat16& h, __nv_bfloat16& l) {
    h = __float2bfloat16_rn(v);
    l = __float2bfloat16_rn(v - __bfloat162float(h));
}
__device__ __forceinline__ uint32_t pack2(__nv_bfloat16 a, __nv_bfloat16 b) {
    return ((uint32_t)__bfloat16_as_ushort(b) << 16) | (uint32_t)__bfloat16_as_ushort(a);
}
__device__ __forceinline__ uint32_t pack2f(float a, float b) {
    __nv_bfloat16 ha, hb; ha = __float2bfloat16_rn(a); hb = __float2bfloat16_rn(b);
    return pack2(ha, hb);
}

// ======== bf16x3 NT mma.sync mainloop: C128x128 = sum_k A[m][k]*B[n][k] =====
// smem stage (16KB): A rows 0..127: [Ah k0..15 | Al k0..15] 64B/row (chunks 0..3),
// then B likewise at +8192. chunk' = chunk ^ ((row>>1)&3). 2 stages = 32KB.
// Each thread ends with acc[4][4][4]; frag (mi,ni): rows wm+mi*16+{lane/4,+8},
// cols wn+ni*8+2*(lane%4)+{0,1}.  (wm=(wid>>2)*64, wn=(wid&3)*32)
#define ISSUE_STAGE(st, k0)                                                     \
    do {                                                                        \
        _Pragma("unroll")                                                       \
        for (int p = 0; p < 4; p++) {                                           \
            int id = tid + (p << 8);                                            \
            int isB = id >> 9;                                                  \
            int rem = id & 511;                                                 \
            int r = rem >> 2, cc = rem & 3;                                     \
            const __nv_bfloat16* src =                                          \
                (isB ? (cc < 2 ? Bh : Bl) : (cc < 2 ? Ah : Al))                 \
                + (size_t)r * (isB ? ldb : lda) + (k0) + ((cc & 1) << 3);       \
            uint32_t dst = sb + (st) * 16384 + isB * 8192 + r * 64              \
                         + ((cc ^ ((r >> 1) & 3)) << 4);                        \
            CP_ASYNC16(dst, src);                                               \
        }                                                                       \
    } while (0)

__device__ __forceinline__ void mma_nt_128(
    const __nv_bfloat16* __restrict__ Ah, const __nv_bfloat16* __restrict__ Al, int lda,
    const __nv_bfloat16* __restrict__ Bh, const __nv_bfloat16* __restrict__ Bl, int ldb,
    int K, float acc[4][4][4], unsigned char* sbuf)
{
    const int tid  = threadIdx.x;
    const int lane = tid & 31;
    const int wid  = tid >> 5;
    const int wm   = (wid >> 2) * 64;
    const int wn   = (wid & 3) * 32;
    const uint32_t sb = smem_u32(sbuf);

    #pragma unroll
    for (int mi = 0; mi < 4; mi++)
        #pragma unroll
        for (int ni = 0; ni < 4; ni++)
            #pragma unroll
            for (int q = 0; q < 4; q++) acc[mi][ni][q] = 0.0f;

    const int nst = K >> 4;
    ISSUE_STAGE(0, 0);
    CP_COMMIT();

    for (int s = 0; s < nst; s++) {
        if (s + 1 < nst) {
            ISSUE_STAGE((s + 1) & 1, (s + 1) << 4);
            CP_COMMIT();
            CP_WAIT(1);
        } else {
            CP_WAIT(0);
        }
        __syncthreads();

        const uint32_t stb = sb + (uint32_t)(s & 1) * 16384;
        uint32_t ah[4][4], al[4][4], bhf[2][4], blf[2][4];
        // A fragments (4 m-frags of 16 rows)
        #pragma unroll
        for (int mi = 0; mi < 4; mi++) {
            int r  = wm + mi * 16 + (lane & 15);
            int ch = (lane >> 4) & 1;
            uint32_t rb = stb + r * 64;
            LDSM4(ah[mi], rb + (((ch)     ^ ((r >> 1) & 3)) << 4));
            LDSM4(al[mi], rb + (((ch + 2) ^ ((r >> 1) & 3)) << 4));
        }
        // B fragments (2 x4 = 4 n-frags of 8 cols)
        #pragma unroll
        for (int nb = 0; nb < 2; nb++) {
            int r  = wn + nb * 16 + (lane & 7) + ((lane & 16) ? 8 : 0);
            int ch = (lane >> 3) & 1;
            uint32_t rb = stb + 8192 + r * 64;
            LDSM4(bhf[nb], rb + (((ch)     ^ ((r >> 1) & 3)) << 4));
            LDSM4(blf[nb], rb + (((ch + 2) ^ ((r >> 1) & 3)) << 4));
        }
        #pragma unroll
        for (int mi = 0; mi < 4; mi++)
            #pragma unroll
            for (int ni = 0; ni < 4; ni++) {
                const int g = ni >> 1, o = (ni & 1) << 1;
                MMA16816(acc[mi][ni], ah[mi], bhf[g][o], bhf[g][o + 1]);
                MMA16816(acc[mi][ni], ah[mi], blf[g][o], blf[g][o + 1]);
                MMA16816(acc[mi][ni], al[mi], bhf[g][o], bhf[g][o + 1]);
            }
        __syncthreads();
    }
}

// ---------------- tiny init --------------------------------------------------
__global__ void zero_l1_kernel(float* l1) {
    if (threadIdx.x < BATCH) l1[threadIdx.x] = 0.0f;
}

// ---------------- conv: z_b and W_c -> bf16 hi/lo ----------------------------
__global__ __launch_bounds__(256) void conv_kernel(const float* __restrict__ zb,
                                                   const float* __restrict__ Wc)
{
    const int NZ = BATCH * FB * SEQ / 4;
    const int NW = FA * HFB / 4;
    int i = blockIdx.x * 256 + threadIdx.x;
    if (i < NZ) {
        float4 v = ((const float4*)zb)[i];
        __nv_bfloat16 h0,l0,h1,l1,h2,l2,h3,l3;
        cvt_hl(v.x,h0,l0); cvt_hl(v.y,h1,l1); cvt_hl(v.z,h2,l2); cvt_hl(v.w,h3,l3);
        ((uint2*)g_vh)[i] = make_uint2(pack2(h0,h1), pack2(h2,h3));
        ((uint2*)g_vl)[i] = make_uint2(pack2(l0,l1), pack2(l2,l3));
    } else if (i < NZ + NW) {
        int j = i - NZ;
        float4 v = ((const float4*)Wc)[j];
        __nv_bfloat16 h0,l0,h1,l1,h2,l2,h3,l3;
        cvt_hl(v.x,h0,l0); cvt_hl(v.y,h1,l1); cvt_hl(v.z,h2,l2); cvt_hl(v.w,h3,l3);
        ((uint2*)g_wh)[j] = make_uint2(pack2(h0,h1), pack2(h2,h3));
        ((uint2*)g_wl)[j] = make_uint2(pack2(l0,l1), pack2(l2,l3));
    }
}

// ---------------- embed: fp32 SIMT GEMM, epilogue -> qT/kT bf16 hi/lo --------
#define BM 128
#define BN 128
#define BK 8
#define TM 8
#define TN 8
__global__ __launch_bounds__(256) void embed_kernel(
    const float* __restrict__ Wa, const float* __restrict__ za,
    const float* __restrict__ Wb, const float* __restrict__ zb)
{
    const int bz = blockIdx.z;
    const int b = bz >> 1, sel = bz & 1;
    const float* __restrict__ A  = sel ? Wb : Wa;                       // [512 x 256]
    const float* __restrict__ Bm = (sel ? zb : za) + (size_t)b*FA*SEQ;  // [256 x 2048]
    __nv_bfloat16* __restrict__ Oh = sel ? g_kh : g_qh;
    __nv_bfloat16* __restrict__ Ol = sel ? g_kl : g_ql;

    __shared__ float As[BK][BM];
    __shared__ float Bs[BK][BN];

    const int tid = threadIdx.x;
    const int m0 = blockIdx.y * BM;
    const int n0 = blockIdx.x * BN;
    const int K = FA;
    const int ty = tid >> 4, tx = tid & 15;

    float acc[TM][TN] = {};

    for (int k0 = 0; k0 < K; k0 += BK) {
        {
            const int mm = tid >> 1, kk = (tid & 1) * 4;
            float4 v = *(const float4*)&A[(size_t)(m0 + mm) * K + k0 + kk];
            As[kk + 0][mm] = v.x; As[kk + 1][mm] = v.y;
            As[kk + 2][mm] = v.z; As[kk + 3][mm] = v.w;
        }
        {
            const int kk = tid >> 5, nn = (tid & 31) * 4;
            *(float4*)&Bs[kk][nn] = *(const float4*)&Bm[(size_t)(k0 + kk) * SEQ + n0 + nn];
        }
        __syncthreads();
        #pragma unroll
        for (int kk = 0; kk < BK; kk++) {
            float a[TM], bb[TN];
            *(float4*)&a[0]  = *(const float4*)&As[kk][ty * TM];
            *(float4*)&a[4]  = *(const float4*)&As[kk][ty * TM + 4];
            *(float4*)&bb[0] = *(const float4*)&Bs[kk][tx * TN];
            *(float4*)&bb[4] = *(const float4*)&Bs[kk][tx * TN + 4];
            #pragma unroll
            for (int i = 0; i < TM; i++)
                #pragma unroll
                for (int j = 0; j < TN; j++)
                    acc[i][j] += a[i] * bb[j];
        }
        __syncthreads();
    }
    // transposed epilogue: m = o = h*64+e -> write [bh][n][e]
    const int mbase = m0 + ty * TM;
    const int h = mbase >> 6, e0 = mbase & 63;
    const size_t bh = (size_t)(b * NHEADS + h);
    #pragma unroll
    for (int j = 0; j < TN; j++) {
        const int n = n0 + tx * TN + j;
        uint32_t hw[4], lw[4];
        #pragma unroll
        for (int p = 0; p < 4; p++) {
            __nv_bfloat16 ha, la, hb, lb;
            cvt_hl(acc[2*p][j], ha, la);
            cvt_hl(acc[2*p+1][j], hb, lb);
            hw[p] = pack2(ha, hb); lw[p] = pack2(la, lb);
        }
        const size_t dst = (bh * SEQ + n) * EMB + e0;
        *(uint4*)(Oh + dst) = make_uint4(hw[0], hw[1], hw[2], hw[3]);
        *(uint4*)(Ol + dst) = make_uint4(lw[0], lw[1], lw[2], lw[3]);
    }
}

// ---------------- pre: mma.sync, K=64, scale+|.|+l1, fp32 out ----------------
// grid (16 ntiles, 16 mtiles, 16 bh)
__global__ __launch_bounds__(256) void pre_mma_kernel(float* __restrict__ l1)
{
    __shared__ __align__(16) unsigned char sbuf[2][16384];
    __shared__ float red[8];
    const int tid = threadIdx.x, lane = tid & 31, wid = tid >> 5;
    const int bh = blockIdx.z, b = bh >> 3;
    const int m0 = blockIdx.y * 128;
    const int n0 = blockIdx.x * 128;

    const __nv_bfloat16* Ah = g_qh + ((size_t)bh * SEQ + m0) * EMB;
    const __nv_bfloat16* Al = g_ql + ((size_t)bh * SEQ + m0) * EMB;
    const __nv_bfloat16* Bh = g_kh + ((size_t)bh * SEQ + n0) * EMB;
    const __nv_bfloat16* Bl = g_kl + ((size_t)bh * SEQ + n0) * EMB;

    float acc[4][4][4];
    mma_nt_128(Ah, Al, EMB, Bh, Bl, EMB, EMB, acc, &sbuf[0][0]);

    const int wm = (wid >> 2) * 64, wn = (wid & 3) * 32;
    float asum = 0.0f;
    #pragma unroll
    for (int mi = 0; mi < 4; mi++) {
        #pragma unroll
        for (int ni = 0; ni < 4; ni++) {
            const int r0 = m0 + wm + mi * 16 + (lane >> 2);
            const int c  = n0 + wn + ni * 8 + ((lane & 3) << 1);
            float v0 = acc[mi][ni][0] * 0.125f;
            float v1 = acc[mi][ni][1] * 0.125f;
            float v2 = acc[mi][ni][2] * 0.125f;
            float v3 = acc[mi][ni][3] * 0.125f;
            asum += fabsf(v0) + fabsf(v1) + fabsf(v2) + fabsf(v3);
            *(float2*)(g_pre + ((size_t)bh * SEQ + r0) * SEQ + c)     = make_float2(v0, v1);
            *(float2*)(g_pre + ((size_t)bh * SEQ + r0 + 8) * SEQ + c) = make_float2(v2, v3);
        }
    }
    #pragma unroll
    for (int o = 16; o > 0; o >>= 1)
        asum += __shfl_xor_sync(0xffffffffu, asum, o);
    if (lane == 0) red[wid] = asum;
    __syncthreads();
    if (tid == 0) {
        float t = 0.0f;
        #pragma unroll
        for (int w = 0; w < 8; w++) t += red[w];
        const float inv = 1.0f / ((float)NHEADS * (float)SEQ * (float)SEQ);
        atomicAdd(&l1[b], t * inv);
    }
}

// ---------------- softmax: fp32 in, bf16 hi/lo coeff out ---------------------
__global__ __launch_bounds__(256) void softmax_kernel()
{
    const int q  = blockIdx.x;
    const int bh = blockIdx.y;
    const size_t row = ((size_t)bh * SEQ + q) * SEQ;
    const float* __restrict__ p = g_pre + row;
    const int tid = threadIdx.x;

    __shared__ float sm[256];

    float vals[8];
    float m = -1e30f;
    #pragma unroll
    for (int i = 0; i < 8; i++) {
        vals[i] = p[tid + i * 256];
        m = fmaxf(m, vals[i]);
    }
    sm[tid] = m; __syncthreads();
    for (int s = 128; s > 0; s >>= 1) {
        if (tid < s) sm[tid] = fmaxf(sm[tid], sm[tid + s]);
        __syncthreads();
    }
    m = sm[0];
    __syncthreads();

    float sum = 0.0f;
    #pragma unroll
    for (int i = 0; i < 8; i++) {
        vals[i] = __expf(vals[i] - m);
        sum += vals[i];
    }
    sm[tid] = sum; __syncthreads();
    for (int s = 128; s > 0; s >>= 1) {
        if (tid < s) sm[tid] += sm[tid + s];
        __syncthreads();
    }
    const float inv = 1.0f / sm[0];
    #pragma unroll
    for (int i = 0; i < 8; i++) {
        float v = vals[i] * inv;
        __nv_bfloat16 h, l;
        cvt_hl(v, h, l);
        g_ch[row + tid + i * 256] = h;
        g_cl[row + tid + i * 256] = l;
    }
}

// ---------------- feat: mma.sync, K=2048, bf16 hi/lo out ---------------------
// grid (2 ntiles, 16 mtiles, 16 bh)
__global__ __launch_bounds__(256) void feat_mma_kernel()
{
    __shared__ __align__(16) unsigned char sbuf[2][16384];
    const int tid = threadIdx.x, lane = tid & 31, wid = tid >> 5;
    const int bh = blockIdx.z, b = bh >> 3, h = bh & 7;
    const int m0 = blockIdx.y * 128;
    const int n0 = blockIdx.x * 128;

    const __nv_bfloat16* Ah = g_ch + ((size_t)bh * SEQ + m0) * SEQ;
    const __nv_bfloat16* Al = g_cl + ((size_t)bh * SEQ + m0) * SEQ;
    const __nv_bfloat16* Bh = g_vh + (size_t)b * FB * SEQ + (size_t)n0 * SEQ;
    const __nv_bfloat16* Bl = g_vl + (size_t)b * FB * SEQ + (size_t)n0 * SEQ;

    float acc[4][4][4];
    mma_nt_128(Ah, Al, SEQ, Bh, Bl, SEQ, SEQ, acc, &sbuf[0][0]);

    const int wm = (wid >> 2) * 64, wn = (wid & 3) * 32;
    #pragma unroll
    for (int mi = 0; mi < 4; mi++) {
        #pragma unroll
        for (int ni = 0; ni < 4; ni++) {
            const int r0 = m0 + wm + mi * 16 + (lane >> 2);
            const int c  = n0 + wn + ni * 8 + ((lane & 3) << 1);
            const size_t d0 = ((size_t)b * SEQ + r0) * HFB + h * FB + c;
            const size_t d1 = ((size_t)b * SEQ + r0 + 8) * HFB + h * FB + c;
            __nv_bfloat16 ha, la, hb, lb;
            cvt_hl(acc[mi][ni][0], ha, la); cvt_hl(acc[mi][ni][1], hb, lb);
            *(uint32_t*)(g_fh + d0) = pack2(ha, hb);
            *(uint32_t*)(g_fl + d0) = pack2(la, lb);
            cvt_hl(acc[mi][ni][2], ha, la); cvt_hl(acc[mi][ni][3], hb, lb);
            *(uint32_t*)(g_fh + d1) = pack2(ha, hb);
            *(uint32_t*)(g_fl + d1) = pack2(la, lb);
        }
    }
}

// ---------------- out: mma.sync, K=2048, fp32 out ----------------------------
// grid (2 ntiles, 16 mtiles, 2 b)
__global__ __launch_bounds__(256) void out_mma_kernel(float* __restrict__ out)
{
    __shared__ __align__(16) unsigned char sbuf[2][16384];
    const int tid = threadIdx.x, lane = tid & 31, wid = tid >> 5;
    const int b = blockIdx.z;
    const int m0 = blockIdx.y * 128;
    const int n0 = blockIdx.x * 128;

    const __nv_bfloat16* Ah = g_fh + ((size_t)b * SEQ + m0) * HFB;
    const __nv_bfloat16* Al = g_fl + ((size_t)b * SEQ + m0) * HFB;
    const __nv_bfloat16* Bh = g_wh + (size_t)n0 * HFB;
    const __nv_bfloat16* Bl = g_wl + (size_t)n0 * HFB;

    float acc[4][4][4];
    mma_nt_128(Ah, Al, HFB, Bh, Bl, HFB, HFB, acc, &sbuf[0][0]);

    const int wm = (wid >> 2) * 64, wn = (wid & 3) * 32;
    #pragma unroll
    for (int mi = 0; mi < 4; mi++) {
        #pragma unroll
        for (int ni = 0; ni < 4; ni++) {
            const int r0 = m0 + wm + mi * 16 + (lane >> 2);
            const int c  = n0 + wn + ni * 8 + ((lane & 3) << 1);
            *(float2*)(out + ((size_t)b * SEQ + r0) * FA + c) =
                make_float2(acc[mi][ni][0], acc[mi][ni][1]);
            *(float2*)(out + ((size_t)b * SEQ + r0 + 8) * FA + c) =
                make_float2(acc[mi][ni][2], acc[mi][ni][3]);
        }
    }
}

// ---------------- launch -----------------------------------------------------
extern "C" void kernel_launch(void* const* d_in, const int* in_sizes, int n_in,
                              void* d_out, int out_size)
{
    const float* z_a = (const float*)d_in[0];   // [2, 256, 2048]
    const float* z_b = (const float*)d_in[1];   // [2, 256, 2048]
    const float* W_a = (const float*)d_in[2];   // [512, 256]
    const float* W_b = (const float*)d_in[3];   // [512, 256]
    const float* W_c = (const float*)d_in[4];   // [256, 2048]
    float* out = (float*)d_out;                 // [2, 2048, 256] then l1 [2]
    float* l1  = out + (size_t)BATCH * SEQ * FA;

    zero_l1_kernel<<<1, 32>>>(l1);

    {
        const int nchunks = (BATCH * FB * SEQ + FA * HFB) / 4;
        conv_kernel<<<(nchunks + 255) / 256, 256>>>(z_b, W_c);
    }
    {
        dim3 grid(SEQ / BN, (NHEADS * EMB) / BM, BATCH * 2);
        embed_kernel<<<grid, 256>>>(W_a, z_a, W_b, z_b);
    }
    {
        dim3 grid(SEQ / 128, SEQ / 128, BATCH * NHEADS);
        pre_mma_kernel<<<grid, 256>>>(l1);
    }
    {
        dim3 grid(SEQ, BATCH * NHEADS);
        softmax_kernel<<<grid, 256>>>();
    }
    {
        dim3 grid(FB / 128, SEQ / 128, BATCH * NHEADS);
        feat_mma_kernel<<<grid, 256>>>();
    }
    {
        dim3 grid(FA / 128, SEQ / 128, BATCH);
        out_mma_kernel<<<grid, 256>>>(out);
    }
}

// round 12
// speedup vs baseline: 2.3267x; 1.0017x over previous
#include <cuda_runtime.h>
#include <cuda_bf16.h>
#include <math.h>
#include <stdint.h>

#define NHEADS 8
#define EMB    64
#define FA     256
#define FB     256
#define BATCH  2
#define SEQ    2048
#define HFB    (NHEADS*FB)   // 2048

// ---------------- scratch (device globals; no allocations allowed) ----------
// qT/kT: [bh][n][e] bf16 hi/lo
__device__ __nv_bfloat16 g_qh[(size_t)BATCH*NHEADS*SEQ*EMB];
__device__ __nv_bfloat16 g_ql[(size_t)BATCH*NHEADS*SEQ*EMB];
__device__ __nv_bfloat16 g_kh[(size_t)BATCH*NHEADS*SEQ*EMB];
__device__ __nv_bfloat16 g_kl[(size_t)BATCH*NHEADS*SEQ*EMB];
// v = z_b: [b][f][k] bf16 hi/lo ; Wc: [o][k] bf16 hi/lo
__device__ __nv_bfloat16 g_vh[(size_t)BATCH*FB*SEQ];
__device__ __nv_bfloat16 g_vl[(size_t)BATCH*FB*SEQ];
__device__ __nv_bfloat16 g_wh[(size_t)FA*HFB];
__device__ __nv_bfloat16 g_wl[(size_t)FA*HFB];
// feat: [b][q][hf] bf16 hi/lo
__device__ __nv_bfloat16 g_fh[(size_t)BATCH*SEQ*HFB];
__device__ __nv_bfloat16 g_fl[(size_t)BATCH*SEQ*HFB];

// ============================ helpers ========================================
__device__ __forceinline__ uint32_t smem_u32(const void* p) {
    uint32_t a;
    asm("{ .reg .u64 t; cvta.to.shared.u64 t, %1; cvt.u32.u64 %0, t; }" : "=r"(a) : "l"(p));
    return a;
}
#define CP_ASYNC16(dst, src) \
    asm volatile("cp.async.cg.shared.global [%0], [%1], 16;" :: "r"(dst), "l"(src))
#define CP_COMMIT() asm volatile("cp.async.commit_group;" ::: "memory")
#define CP_WAIT(n)  asm volatile("cp.async.wait_group %0;" :: "n"(n) : "memory")

#define LDSM4(r, addr) \
    asm volatile("ldmatrix.sync.aligned.m8n8.x4.shared.b16 {%0,%1,%2,%3}, [%4];" \
        : "=r"((r)[0]), "=r"((r)[1]), "=r"((r)[2]), "=r"((r)[3]) : "r"(addr))

#define MMA16816(d, a, b0, b1)                                                  \
    asm volatile("mma.sync.aligned.m16n8k16.row.col.f32.bf16.bf16.f32 "         \
        "{%0,%1,%2,%3}, {%4,%5,%6,%7}, {%8,%9}, {%0,%1,%2,%3};"                 \
        : "+f"((d)[0]), "+f"((d)[1]), "+f"((d)[2]), "+f"((d)[3])                \
        : "r"((a)[0]), "r"((a)[1]), "r"((a)[2]), "r"((a)[3]), "r"(b0), "r"(b1))

__device__ __forceinline__ void cvt_hl(float v, __nv_bfloat16& h, __nv_bfloat16& l) {
    h = __float2bfloat16_rn(v);
    l = __float2bfloat16_rn(v - __bfloat162float(h));
}
__device__ __forceinline__ uint32_t pack2(__nv_bfloat16 a, __nv_bfloat16 b) {
    return ((uint32_t)__bfloat16_as_ushort(b) << 16) | (uint32_t)__bfloat16_as_ushort(a);
}

// ---- tile stage format (proven in R11): per 16-k slice a row is 64B:
// [hi: 2 x 16B chunks | lo: 2 x 16B chunks], chunk' = chunk ^ ((row>>1)&3).
// A tile of R rows x (NS*16) k = NS stages of R*64 bytes.
template<int R, int NS>
__device__ __forceinline__ void issue_tile(uint32_t sb,
    const __nv_bfloat16* __restrict__ Gh, const __nv_bfloat16* __restrict__ Gl, int ld)
{
    const int tid = threadIdx.x;
    constexpr int CPT = (R * NS * 4) / 256;
    #pragma unroll
    for (int p = 0; p < CPT; p++) {
        int id  = tid + (p << 8);
        int s   = id / (R * 4);
        int rem = id - s * (R * 4);
        int r   = rem >> 2, cc = rem & 3;
        const __nv_bfloat16* src = (cc < 2 ? Gh : Gl)
            + (size_t)r * ld + s * 16 + ((cc & 1) << 3);
        uint32_t dst = sb + s * (R * 64) + r * 64 + ((cc ^ ((r >> 1) & 3)) << 4);
        CP_ASYNC16(dst, src);
    }
}

// A frags (rows wm..wm+31) from one stage (proven pattern)
__device__ __forceinline__ void lda_frag(uint32_t stb, int wm, int lane,
                                         uint32_t ah[2][4], uint32_t al[2][4])
{
    #pragma unroll
    for (int mi = 0; mi < 2; mi++) {
        int r  = wm + mi * 16 + (lane & 15);
        int ch = (lane >> 4) & 1;
        uint32_t rb = stb + r * 64;
        LDSM4(ah[mi], rb + (((ch)     ^ ((r >> 1) & 3)) << 4));
        LDSM4(al[mi], rb + (((ch + 2) ^ ((r >> 1) & 3)) << 4));
    }
}
// B frags (rows wn..wn+31) from one stage (proven pattern)
__device__ __forceinline__ void ldb_frag(uint32_t stb, int wn, int lane,
                                         uint32_t bh_[2][4], uint32_t bl_[2][4])
{
    #pragma unroll
    for (int nb = 0; nb < 2; nb++) {
        int r  = wn + nb * 16 + (lane & 7) + ((lane & 16) ? 8 : 0);
        int ch = (lane >> 3) & 1;
        uint32_t rb = stb + r * 64;
        LDSM4(bh_[nb], rb + (((ch)     ^ ((r >> 1) & 3)) << 4));
        LDSM4(bl_[nb], rb + (((ch + 2) ^ ((r >> 1) & 3)) << 4));
    }
}

// ---------------- fused attention smem layout (dynamic) ----------------------
// Q: 64 rows x 4 stages  = 16384
// K: 128 rows x 4 stages = 32768
// P: 64 rows x 8 stages  = 32768
// V0/V1: 128 rows x 8 stages = 65536 each
#define OQ   0
#define OK_  16384
#define OP   49152
#define OV0  81920
#define OV1  147456
#define OL   212992
#define ORED 213248
#define SMEM_FUSED 213504

__device__ __forceinline__ void pv_gemm(uint32_t pb, uint32_t vb, int wm, int wn,
                                        int lane, float (&oacc)[2][4][4])
{
    #pragma unroll
    for (int ks = 0; ks < 8; ks++) {
        uint32_t ah[2][4], al[2][4], bh_[2][4], bl_[2][4];
        lda_frag(pb + ks * 4096, wm, lane, ah, al);
        ldb_frag(vb + ks * 8192, wn, lane, bh_, bl_);
        #pragma unroll
        for (int mi = 0; mi < 2; mi++)
            #pragma unroll
            for (int ni = 0; ni < 4; ni++) {
                const int g = ni >> 1, o = (ni & 1) << 1;
                MMA16816(oacc[mi][ni], ah[mi], bh_[g][o], bh_[g][o + 1]);
                MMA16816(oacc[mi][ni], ah[mi], bl_[g][o], bl_[g][o + 1]);
                MMA16816(oacc[mi][ni], al[mi], bh_[g][o], bh_[g][o + 1]);
            }
    }
}

// ============ fused: pre + softmax(+l1) + feat, per (bh, 64-q tile) ==========
__global__ __launch_bounds__(256, 1) void attn_fused_kernel(float* __restrict__ l1)
{
    extern __shared__ char SM[];
    const uint32_t SB = smem_u32(SM);
    const int tid = threadIdx.x, lane = tid & 31, wid = tid >> 5;
    const int wm = (wid >> 2) * 32, wn = (wid & 3) * 32;
    const int qt = blockIdx.x, bh = blockIdx.y;
    const int b = bh >> 3, h = bh & 7;
    const int qbase = qt * 64;
    float* slf = (float*)(SM + OL);
    float* red = (float*)(SM + ORED);

    const __nv_bfloat16* Qh = g_qh + ((size_t)bh * SEQ + qbase) * EMB;
    const __nv_bfloat16* Ql = g_ql + ((size_t)bh * SEQ + qbase) * EMB;
    const __nv_bfloat16* Kh = g_kh + (size_t)bh * SEQ * EMB;
    const __nv_bfloat16* Kl = g_kl + (size_t)bh * SEQ * EMB;
    const __nv_bfloat16* Vh0 = g_vh + (size_t)b * FB * SEQ;
    const __nv_bfloat16* Vl0 = g_vl + (size_t)b * FB * SEQ;
    const __nv_bfloat16* Vh1 = Vh0 + (size_t)128 * SEQ;
    const __nv_bfloat16* Vl1 = Vl0 + (size_t)128 * SEQ;

    if (tid < 64) slf[tid] = 0.0f;

    // prologue: group1 = Q + K0, group2 = V0_0, group3 = V1_0
    issue_tile<64, 4>(SB + OQ, Qh, Ql, EMB);
    issue_tile<128, 4>(SB + OK_, Kh, Kl, EMB);
    CP_COMMIT();
    issue_tile<128, 8>(SB + OV0, Vh0, Vl0, SEQ);
    CP_COMMIT();
    issue_tile<128, 8>(SB + OV1, Vh1, Vl1, SEQ);
    CP_COMMIT();

    float oacc0[2][4][4] = {};
    float oacc1[2][4][4] = {};
    float l1acc = 0.0f;

    for (int j = 0; j < 16; j++) {
        CP_WAIT(2);             // Q+K_j arrived
        __syncthreads();

        // ---- S = Q x K^T (64 x 128, K=64), bf16x3 ----
        float sacc[2][4][4] = {};
        #pragma unroll
        for (int ks = 0; ks < 4; ks++) {
            uint32_t ah[2][4], al[2][4], bh_[2][4], bl_[2][4];
            lda_frag(SB + OQ + ks * 4096, wm, lane, ah, al);
            ldb_frag(SB + OK_ + ks * 8192, wn, lane, bh_, bl_);
            #pragma unroll
            for (int mi = 0; mi < 2; mi++)
                #pragma unroll
                for (int ni = 0; ni < 4; ni++) {
                    const int g = ni >> 1, o = (ni & 1) << 1;
                    MMA16816(sacc[mi][ni], ah[mi], bh_[g][o], bh_[g][o + 1]);
                    MMA16816(sacc[mi][ni], ah[mi], bl_[g][o], bl_[g][o + 1]);
                    MMA16816(sacc[mi][ni], al[mi], bh_[g][o], bh_[g][o + 1]);
                }
        }
        __syncthreads();        // done reading K_j
        if (j + 1 < 16)
            issue_tile<128, 4>(SB + OK_, Kh + (size_t)(j + 1) * 128 * EMB,
                               Kl + (size_t)(j + 1) * 128 * EMB, EMB);
        CP_COMMIT();

        // ---- convert: s*0.125 -> |s| (l1), exp -> P hi/lo smem + row sums ----
        #pragma unroll
        for (int mi = 0; mi < 2; mi++) {
            const int r0 = wm + mi * 16 + (lane >> 2);
            const int r1 = r0 + 8;
            float rs0 = 0.0f, rs1 = 0.0f;
            #pragma unroll
            for (int ni = 0; ni < 4; ni++) {
                const int c  = wn + ni * 8 + ((lane & 3) << 1);
                const int st = c >> 4, k = c & 15;
                const int ch = k >> 3, intra = (k & 7) * 2;
                float s0 = sacc[mi][ni][0] * 0.125f;
                float s1 = sacc[mi][ni][1] * 0.125f;
                float s2 = sacc[mi][ni][2] * 0.125f;
                float s3 = sacc[mi][ni][3] * 0.125f;
                l1acc += fabsf(s0) + fabsf(s1) + fabsf(s2) + fabsf(s3);
                float p0 = __expf(s0), p1 = __expf(s1);
                float p2 = __expf(s2), p3 = __expf(s3);
                rs0 += p0 + p1; rs1 += p2 + p3;
                __nv_bfloat16 H0, L0, H1, L1;
                cvt_hl(p0, H0, L0); cvt_hl(p1, H1, L1);
                const uint32_t b0 = OP + st * 4096 + r0 * 64;
                *(uint32_t*)(SM + b0 + (((ch)     ^ ((r0 >> 1) & 3)) << 4) + intra) = pack2(H0, H1);
                *(uint32_t*)(SM + b0 + (((ch + 2) ^ ((r0 >> 1) & 3)) << 4) + intra) = pack2(L0, L1);
                cvt_hl(p2, H0, L0); cvt_hl(p3, H1, L1);
                const uint32_t b1 = OP + st * 4096 + r1 * 64;
                *(uint32_t*)(SM + b1 + (((ch)     ^ ((r1 >> 1) & 3)) << 4) + intra) = pack2(H0, H1);
                *(uint32_t*)(SM + b1 + (((ch + 2) ^ ((r1 >> 1) & 3)) << 4) + intra) = pack2(L0, L1);
            }
            rs0 += __shfl_xor_sync(0xffffffffu, rs0, 1);
            rs0 += __shfl_xor_sync(0xffffffffu, rs0, 2);
            rs1 += __shfl_xor_sync(0xffffffffu, rs1, 1);
            rs1 += __shfl_xor_sync(0xffffffffu, rs1, 2);
            if ((lane & 3) == 0) {
                atomicAdd(&slf[r0], rs0);
                atomicAdd(&slf[r1], rs1);
            }
        }

        CP_WAIT(2);             // V0_j arrived
        __syncthreads();        // also publishes P + l

        pv_gemm(SB + OP, SB + OV0, wm, wn, lane, oacc0);
        __syncthreads();        // done reading V0_j
        if (j + 1 < 16)
            issue_tile<128, 8>(SB + OV0, Vh0 + (j + 1) * 128, Vl0 + (j + 1) * 128, SEQ);
        CP_COMMIT();

        CP_WAIT(2);             // V1_j arrived
        __syncthreads();
        pv_gemm(SB + OP, SB + OV1, wm, wn, lane, oacc1);
        __syncthreads();        // done reading V1_j (and P)
        if (j + 1 < 16)
            issue_tile<128, 8>(SB + OV1, Vh1 + (j + 1) * 128, Vl1 + (j + 1) * 128, SEQ);
        CP_COMMIT();
    }

    __syncthreads();

    // ---- epilogue: O / l -> feat hi/lo ----
    #pragma unroll
    for (int mi = 0; mi < 2; mi++) {
        const int r0 = wm + mi * 16 + (lane >> 2);
        const float inv0 = 1.0f / slf[r0];
        const float inv1 = 1.0f / slf[r0 + 8];
        #pragma unroll
        for (int hv = 0; hv < 2; hv++) {
            #pragma unroll
            for (int ni = 0; ni < 4; ni++) {
                const float* a = hv ? oacc1[mi][ni] : oacc0[mi][ni];
                const int c = hv * 128 + wn + ni * 8 + ((lane & 3) << 1);
                const size_t d0 = ((size_t)b * SEQ + qbase + r0) * HFB + h * FB + c;
                const size_t d1 = ((size_t)b * SEQ + qbase + r0 + 8) * HFB + h * FB + c;
                float v0 = a[0] * inv0, v1 = a[1] * inv0;
                float v2 = a[2] * inv1, v3 = a[3] * inv1;
                __nv_bfloat16 H0, L0, H1, L1;
                cvt_hl(v0, H0, L0); cvt_hl(v1, H1, L1);
                *(uint32_t*)(g_fh + d0) = pack2(H0, H1);
                *(uint32_t*)(g_fl + d0) = pack2(L0, L1);
                cvt_hl(v2, H0, L0); cvt_hl(v3, H1, L1);
                *(uint32_t*)(g_fh + d1) = pack2(H0, H1);
                *(uint32_t*)(g_fl + d1) = pack2(L0, L1);
            }
        }
    }

    // ---- l1 reduction ----
    #pragma unroll
    for (int o = 16; o > 0; o >>= 1)
        l1acc += __shfl_xor_sync(0xffffffffu, l1acc, o);
    if (lane == 0) red[wid] = l1acc;
    __syncthreads();
    if (tid == 0) {
        float t = 0.0f;
        #pragma unroll
        for (int w = 0; w < 8; w++) t += red[w];
        atomicAdd(&l1[b], t * (1.0f / (8.0f * 2048.0f * 2048.0f)));
    }
}

// ---------------- tiny init --------------------------------------------------
__global__ void zero_l1_kernel(float* l1) {
    if (threadIdx.x < BATCH) l1[threadIdx.x] = 0.0f;
}

// ---------------- conv: z_b and W_c -> bf16 hi/lo ----------------------------
__global__ __launch_bounds__(256) void conv_kernel(const float* __restrict__ zb,
                                                   const float* __restrict__ Wc)
{
    const int NZ = BATCH * FB * SEQ / 4;
    const int NW = FA * HFB / 4;
    int i = blockIdx.x * 256 + threadIdx.x;
    if (i < NZ) {
        float4 v = ((const float4*)zb)[i];
        __nv_bfloat16 h0,l0,h1,l1,h2,l2,h3,l3;
        cvt_hl(v.x,h0,l0); cvt_hl(v.y,h1,l1); cvt_hl(v.z,h2,l2); cvt_hl(v.w,h3,l3);
        ((uint2*)g_vh)[i] = make_uint2(pack2(h0,h1), pack2(h2,h3));
        ((uint2*)g_vl)[i] = make_uint2(pack2(l0,l1), pack2(l2,l3));
    } else if (i < NZ + NW) {
        int j = i - NZ;
        float4 v = ((const float4*)Wc)[j];
        __nv_bfloat16 h0,l0,h1,l1,h2,l2,h3,l3;
        cvt_hl(v.x,h0,l0); cvt_hl(v.y,h1,l1); cvt_hl(v.z,h2,l2); cvt_hl(v.w,h3,l3);
        ((uint2*)g_wh)[j] = make_uint2(pack2(h0,h1), pack2(h2,h3));
        ((uint2*)g_wl)[j] = make_uint2(pack2(l0,l1), pack2(l2,l3));
    }
}

// ---------------- embed: fp32 SIMT GEMM, epilogue -> qT/kT bf16 hi/lo --------
#define BM 128
#define BN 128
#define BK 8
#define TM 8
#define TN 8
__global__ __launch_bounds__(256) void embed_kernel(
    const float* __restrict__ Wa, const float* __restrict__ za,
    const float* __restrict__ Wb, const float* __restrict__ zb)
{
    const int bz = blockIdx.z;
    const int b = bz >> 1, sel = bz & 1;
    const float* __restrict__ A  = sel ? Wb : Wa;                       // [512 x 256]
    const float* __restrict__ Bm = (sel ? zb : za) + (size_t)b*FA*SEQ;  // [256 x 2048]
    __nv_bfloat16* __restrict__ Oh = sel ? g_kh : g_qh;
    __nv_bfloat16* __restrict__ Ol = sel ? g_kl : g_ql;

    __shared__ float As[BK][BM];
    __shared__ float Bs[BK][BN];

    const int tid = threadIdx.x;
    const int m0 = blockIdx.y * BM;
    const int n0 = blockIdx.x * BN;
    const int K = FA;
    const int ty = tid >> 4, tx = tid & 15;

    float acc[TM][TN] = {};

    for (int k0 = 0; k0 < K; k0 += BK) {
        {
            const int mm = tid >> 1, kk = (tid & 1) * 4;
            float4 v = *(const float4*)&A[(size_t)(m0 + mm) * K + k0 + kk];
            As[kk + 0][mm] = v.x; As[kk + 1][mm] = v.y;
            As[kk + 2][mm] = v.z; As[kk + 3][mm] = v.w;
        }
        {
            const int kk = tid >> 5, nn = (tid & 31) * 4;
            *(float4*)&Bs[kk][nn] = *(const float4*)&Bm[(size_t)(k0 + kk) * SEQ + n0 + nn];
        }
        __syncthreads();
        #pragma unroll
        for (int kk = 0; kk < BK; kk++) {
            float a[TM], bb[TN];
            *(float4*)&a[0]  = *(const float4*)&As[kk][ty * TM];
            *(float4*)&a[4]  = *(const float4*)&As[kk][ty * TM + 4];
            *(float4*)&bb[0] = *(const float4*)&Bs[kk][tx * TN];
            *(float4*)&bb[4] = *(const float4*)&Bs[kk][tx * TN + 4];
            #pragma unroll
            for (int i = 0; i < TM; i++)
                #pragma unroll
                for (int j = 0; j < TN; j++)
                    acc[i][j] += a[i] * bb[j];
        }
        __syncthreads();
    }
    // transposed epilogue: m = o = h*64+e -> write [bh][n][e]
    const int mbase = m0 + ty * TM;
    const int h = mbase >> 6, e0 = mbase & 63;
    const size_t bh = (size_t)(b * NHEADS + h);
    #pragma unroll
    for (int j = 0; j < TN; j++) {
        const int n = n0 + tx * TN + j;
        uint32_t hw[4], lw[4];
        #pragma unroll
        for (int p = 0; p < 4; p++) {
            __nv_bfloat16 ha, la, hb, lb;
            cvt_hl(acc[2*p][j], ha, la);
            cvt_hl(acc[2*p+1][j], hb, lb);
            hw[p] = pack2(ha, hb); lw[p] = pack2(la, lb);
        }
        const size_t dst = (bh * SEQ + n) * EMB + e0;
        *(uint4*)(Oh + dst) = make_uint4(hw[0], hw[1], hw[2], hw[3]);
        *(uint4*)(Ol + dst) = make_uint4(lw[0], lw[1], lw[2], lw[3]);
    }
}

// ---------------- out: mma.sync bf16x3, K=2048, fp32 out ---------------------
#define ISSUE_STAGE(st, k0)                                                     \
    do {                                                                        \
        _Pragma("unroll")                                                       \
        for (int p = 0; p < 4; p++) {                                           \
            int id = tid + (p << 8);                                            \
            int isB = id >> 9;                                                  \
            int rem = id & 511;                                                 \
            int r = rem >> 2, cc = rem & 3;                                     \
            const __nv_bfloat16* src =                                          \
                (isB ? (cc < 2 ? Bh : Bl) : (cc < 2 ? Ah : Al))                 \
                + (size_t)r * (isB ? ldb : lda) + (k0) + ((cc & 1) << 3);       \
            uint32_t dst = sb + (st) * 16384 + isB * 8192 + r * 64              \
                         + ((cc ^ ((r >> 1) & 3)) << 4);                        \
            CP_ASYNC16(dst, src);                                               \
        }                                                                       \
    } while (0)

__device__ __forceinline__ void mma_nt_128(
    const __nv_bfloat16* __restrict__ Ah, const __nv_bfloat16* __restrict__ Al, int lda,
    const __nv_bfloat16* __restrict__ Bh, const __nv_bfloat16* __restrict__ Bl, int ldb,
    int K, float acc[4][4][4], unsigned char* sbuf)
{
    const int tid  = threadIdx.x;
    const int lane = tid & 31;
    const int wid  = tid >> 5;
    const int wm   = (wid >> 2) * 64;
    const int wn   = (wid & 3) * 32;
    const uint32_t sb = smem_u32(sbuf);

    #pragma unroll
    for (int mi = 0; mi < 4; mi++)
        #pragma unroll
        for (int ni = 0; ni < 4; ni++)
            #pragma unroll
            for (int q = 0; q < 4; q++) acc[mi][ni][q] = 0.0f;

    const int nst = K >> 4;
    ISSUE_STAGE(0, 0);
    CP_COMMIT();

    for (int s = 0; s < nst; s++) {
        if (s + 1 < nst) {
            ISSUE_STAGE((s + 1) & 1, (s + 1) << 4);
            CP_COMMIT();
            CP_WAIT(1);
        } else {
            CP_WAIT(0);
        }
        __syncthreads();

        const uint32_t stb = sb + (uint32_t)(s & 1) * 16384;
        uint32_t ah[4][4], al[4][4], bhf[2][4], blf[2][4];
        #pragma unroll
        for (int mi = 0; mi < 4; mi++) {
            int r  = wm + mi * 16 + (lane & 15);
            int ch = (lane >> 4) & 1;
            uint32_t rb = stb + r * 64;
            LDSM4(ah[mi], rb + (((ch)     ^ ((r >> 1) & 3)) << 4));
            LDSM4(al[mi], rb + (((ch + 2) ^ ((r >> 1) & 3)) << 4));
        }
        #pragma unroll
        for (int nb = 0; nb < 2; nb++) {
            int r  = wn + nb * 16 + (lane & 7) + ((lane & 16) ? 8 : 0);
            int ch = (lane >> 3) & 1;
            uint32_t rb = stb + 8192 + r * 64;
            LDSM4(bhf[nb], rb + (((ch)     ^ ((r >> 1) & 3)) << 4));
            LDSM4(blf[nb], rb + (((ch + 2) ^ ((r >> 1) & 3)) << 4));
        }
        #pragma unroll
        for (int mi = 0; mi < 4; mi++)
            #pragma unroll
            for (int ni = 0; ni < 4; ni++) {
                const int g = ni >> 1, o = (ni & 1) << 1;
                MMA16816(acc[mi][ni], ah[mi], bhf[g][o], bhf[g][o + 1]);
                MMA16816(acc[mi][ni], ah[mi], blf[g][o], blf[g][o + 1]);
                MMA16816(acc[mi][ni], al[mi], bhf[g][o], bhf[g][o + 1]);
            }
        __syncthreads();
    }
}

__global__ __launch_bounds__(256) void out_mma_kernel(float* __restrict__ out)
{
    __shared__ __align__(16) unsigned char sbuf[2][16384];
    const int tid = threadIdx.x, lane = tid & 31, wid = tid >> 5;
    const int b = blockIdx.z;
    const int m0 = blockIdx.y * 128;
    const int n0 = blockIdx.x * 128;

    const __nv_bfloat16* Ah = g_fh + ((size_t)b * SEQ + m0) * HFB;
    const __nv_bfloat16* Al = g_fl + ((size_t)b * SEQ + m0) * HFB;
    const __nv_bfloat16* Bh = g_wh + (size_t)n0 * HFB;
    const __nv_bfloat16* Bl = g_wl + (size_t)n0 * HFB;

    float acc[4][4][4];
    mma_nt_128(Ah, Al, HFB, Bh, Bl, HFB, HFB, acc, &sbuf[0][0]);

    const int wm = (wid >> 2) * 64, wn = (wid & 3) * 32;
    #pragma unroll
    for (int mi = 0; mi < 4; mi++) {
        #pragma unroll
        for (int ni = 0; ni < 4; ni++) {
            const int r0 = m0 + wm + mi * 16 + (lane >> 2);
            const int c  = n0 + wn + ni * 8 + ((lane & 3) << 1);
            *(float2*)(out + ((size_t)b * SEQ + r0) * FA + c) =
                make_float2(acc[mi][ni][0], acc[mi][ni][1]);
            *(float2*)(out + ((size_t)b * SEQ + r0 + 8) * FA + c) =
                make_float2(acc[mi][ni][2], acc[mi][ni][3]);
        }
    }
}

// ---------------- launch -----------------------------------------------------
extern "C" void kernel_launch(void* const* d_in, const int* in_sizes, int n_in,
                              void* d_out, int out_size)
{
    const float* z_a = (const float*)d_in[0];   // [2, 256, 2048]
    const float* z_b = (const float*)d_in[1];   // [2, 256, 2048]
    const float* W_a = (const float*)d_in[2];   // [512, 256]
    const float* W_b = (const float*)d_in[3];   // [512, 256]
    const float* W_c = (const float*)d_in[4];   // [256, 2048]
    float* out = (float*)d_out;                 // [2, 2048, 256] then l1 [2]
    float* l1  = out + (size_t)BATCH * SEQ * FA;

    cudaFuncSetAttribute(attn_fused_kernel,
                         cudaFuncAttributeMaxDynamicSharedMemorySize, SMEM_FUSED);

    zero_l1_kernel<<<1, 32>>>(l1);

    {
        const int nchunks = (BATCH * FB * SEQ + FA * HFB) / 4;
        conv_kernel<<<(nchunks + 255) / 256, 256>>>(z_b, W_c);
    }
    {
        dim3 grid(SEQ / BN, (NHEADS * EMB) / BM, BATCH * 2);
        embed_kernel<<<grid, 256>>>(W_a, z_a, W_b, z_b);
    }
    {
        dim3 grid(SEQ / 64, BATCH * NHEADS);
        attn_fused_kernel<<<grid, 256, SMEM_FUSED>>>(l1);
    }
    {
        dim3 grid(FA / 128, SEQ / 128, BATCH);
        out_mma_kernel<<<grid, 256>>>(out);
    }
}

// round 13
// speedup vs baseline: 2.3555x; 1.0123x over previous
#include <cuda_runtime.h>
#include <cuda_bf16.h>
#include <math.h>
#include <stdint.h>

#define NHEADS 8
#define EMB    64
#define FA     256
#define FB     256
#define BATCH  2
#define SEQ    2048
#define HFB    (NHEADS*FB)   // 2048

// q pre-scale: 0.125 (1/sqrt(64)) * log2(e) so S is in log2 domain
#define QSCALE 0.18033688011112042f
// l1 compensation: |s_nat| = |s_log2| * ln2
#define L1SCALE (0.6931471805599453f / 33554432.0f)   // ln2 / (8*2048*2048)

// ---------------- scratch (device globals; no allocations allowed) ----------
// qT/kT: [bh][n][e] bf16 hi/lo  (q pre-scaled by QSCALE)
__device__ __nv_bfloat16 g_qh[(size_t)BATCH*NHEADS*SEQ*EMB];
__device__ __nv_bfloat16 g_ql[(size_t)BATCH*NHEADS*SEQ*EMB];
__device__ __nv_bfloat16 g_kh[(size_t)BATCH*NHEADS*SEQ*EMB];
__device__ __nv_bfloat16 g_kl[(size_t)BATCH*NHEADS*SEQ*EMB];
// v = z_b: [b][f][k] bf16 hi/lo ; Wc: [o][k] bf16 hi/lo
__device__ __nv_bfloat16 g_vh[(size_t)BATCH*FB*SEQ];
__device__ __nv_bfloat16 g_vl[(size_t)BATCH*FB*SEQ];
__device__ __nv_bfloat16 g_wh[(size_t)FA*HFB];
__device__ __nv_bfloat16 g_wl[(size_t)FA*HFB];
// feat: [b][q][hf] bf16 hi/lo
__device__ __nv_bfloat16 g_fh[(size_t)BATCH*SEQ*HFB];
__device__ __nv_bfloat16 g_fl[(size_t)BATCH*SEQ*HFB];

// ============================ helpers ========================================
__device__ __forceinline__ uint32_t smem_u32(const void* p) {
    uint32_t a;
    asm("{ .reg .u64 t; cvta.to.shared.u64 t, %1; cvt.u32.u64 %0, t; }" : "=r"(a) : "l"(p));
    return a;
}
#define CP_ASYNC16(dst, src) \
    asm volatile("cp.async.cg.shared.global [%0], [%1], 16;" :: "r"(dst), "l"(src))
#define CP_COMMIT() asm volatile("cp.async.commit_group;" ::: "memory")
#define CP_WAIT(n)  asm volatile("cp.async.wait_group %0;" :: "n"(n) : "memory")

#define LDSM4(r, addr) \
    asm volatile("ldmatrix.sync.aligned.m8n8.x4.shared.b16 {%0,%1,%2,%3}, [%4];" \
        : "=r"((r)[0]), "=r"((r)[1]), "=r"((r)[2]), "=r"((r)[3]) : "r"(addr))

#define MMA16816(d, a, b0, b1)                                                  \
    asm volatile("mma.sync.aligned.m16n8k16.row.col.f32.bf16.bf16.f32 "         \
        "{%0,%1,%2,%3}, {%4,%5,%6,%7}, {%8,%9}, {%0,%1,%2,%3};"                 \
        : "+f"((d)[0]), "+f"((d)[1]), "+f"((d)[2]), "+f"((d)[3])                \
        : "r"((a)[0]), "r"((a)[1]), "r"((a)[2]), "r"((a)[3]), "r"(b0), "r"(b1))

__device__ __forceinline__ void cvt_hl(float v, __nv_bfloat16& h, __nv_bfloat16& l) {
    h = __float2bfloat16_rn(v);
    l = __float2bfloat16_rn(v - __bfloat162float(h));
}
__device__ __forceinline__ uint32_t pack2(__nv_bfloat16 a, __nv_bfloat16 b) {
    return ((uint32_t)__bfloat16_as_ushort(b) << 16) | (uint32_t)__bfloat16_as_ushort(a);
}
__device__ __forceinline__ float ex2(float x) {
    float y; asm("ex2.approx.f32 %0, %1;" : "=f"(y) : "f"(x)); return y;
}

// ---- tile stage format (proven): per 16-k slice a row is 64B:
// [hi: 2 x 16B chunks | lo: 2 x 16B chunks], chunk' = chunk ^ ((row>>1)&3).
template<int R, int NS, int NT>
__device__ __forceinline__ void issue_tile(uint32_t sb,
    const __nv_bfloat16* __restrict__ Gh, const __nv_bfloat16* __restrict__ Gl, int ld)
{
    const int tid = threadIdx.x;
    constexpr int CPT = (R * NS * 4) / NT;
    #pragma unroll
    for (int p = 0; p < CPT; p++) {
        int id  = tid + p * NT;
        int s   = id / (R * 4);
        int rem = id - s * (R * 4);
        int r   = rem >> 2, cc = rem & 3;
        const __nv_bfloat16* src = (cc < 2 ? Gh : Gl)
            + (size_t)r * ld + s * 16 + ((cc & 1) << 3);
        uint32_t dst = sb + s * (R * 64) + r * 64 + ((cc ^ ((r >> 1) & 3)) << 4);
        CP_ASYNC16(dst, src);
    }
}

// A frags, single 16-row m-frag (rows wm..wm+15)
__device__ __forceinline__ void lda_frag1(uint32_t stb, int wm, int lane,
                                          uint32_t ah[4], uint32_t al[4])
{
    int r  = wm + (lane & 15);
    int ch = (lane >> 4) & 1;
    uint32_t rb = stb + r * 64;
    LDSM4(ah, rb + (((ch)     ^ ((r >> 1) & 3)) << 4));
    LDSM4(al, rb + (((ch + 2) ^ ((r >> 1) & 3)) << 4));
}
// B frags (rows wn..wn+31)
__device__ __forceinline__ void ldb_frag(uint32_t stb, int wn, int lane,
                                         uint32_t bh_[2][4], uint32_t bl_[2][4])
{
    #pragma unroll
    for (int nb = 0; nb < 2; nb++) {
        int r  = wn + nb * 16 + (lane & 7) + ((lane & 16) ? 8 : 0);
        int ch = (lane >> 3) & 1;
        uint32_t rb = stb + r * 64;
        LDSM4(bh_[nb], rb + (((ch)     ^ ((r >> 1) & 3)) << 4));
        LDSM4(bl_[nb], rb + (((ch + 2) ^ ((r >> 1) & 3)) << 4));
    }
}

// ---------------- fused attention smem layout (dynamic) ----------------------
#define OQ   0          // 64 x 4 stages  = 16384
#define OK_  16384      // 128 x 4 stages = 32768
#define OP   49152      // 64 x 8 stages  = 32768
#define OV0  81920      // 128 x 8 stages = 65536
#define OV1  147456     // 128 x 8 stages = 65536
#define OL   212992     // 64 floats
#define ORED 213248     // 16 floats
#define SMEM_FUSED 213504

// ============ fused: pre + softmax(+l1) + feat, per (bh, 64-q tile) ==========
// 512 threads, 16 warps as 4(m) x 4(n): wm = (wid>>2)*16, wn = (wid&3)*32
__global__ __launch_bounds__(512, 1) void attn_fused_kernel(float* __restrict__ l1)
{
    extern __shared__ char SM[];
    const uint32_t SB = smem_u32(SM);
    const int tid = threadIdx.x, lane = tid & 31, wid = tid >> 5;
    const int wm = (wid >> 2) * 16, wn = (wid & 3) * 32;
    const int qt = blockIdx.x, bh = blockIdx.y;
    const int b = bh >> 3, h = bh & 7;
    const int qbase = qt * 64;
    float* slf = (float*)(SM + OL);
    float* red = (float*)(SM + ORED);

    const __nv_bfloat16* Qh = g_qh + ((size_t)bh * SEQ + qbase) * EMB;
    const __nv_bfloat16* Ql = g_ql + ((size_t)bh * SEQ + qbase) * EMB;
    const __nv_bfloat16* Kh = g_kh + (size_t)bh * SEQ * EMB;
    const __nv_bfloat16* Kl = g_kl + (size_t)bh * SEQ * EMB;
    const __nv_bfloat16* Vh0 = g_vh + (size_t)b * FB * SEQ;
    const __nv_bfloat16* Vl0 = g_vl + (size_t)b * FB * SEQ;
    const __nv_bfloat16* Vh1 = Vh0 + (size_t)128 * SEQ;
    const __nv_bfloat16* Vl1 = Vl0 + (size_t)128 * SEQ;

    if (tid < 64) slf[tid] = 0.0f;

    // prologue: G0 = Q + K_0 ; G1 = V_0 (both halves)
    issue_tile<64, 4, 512>(SB + OQ, Qh, Ql, EMB);
    issue_tile<128, 4, 512>(SB + OK_, Kh, Kl, EMB);
    CP_COMMIT();
    issue_tile<128, 8, 512>(SB + OV0, Vh0, Vl0, SEQ);
    issue_tile<128, 8, 512>(SB + OV1, Vh1, Vl1, SEQ);
    CP_COMMIT();

    float oacc0[4][4] = {};
    float oacc1[4][4] = {};
    float l1acc = 0.0f;

    for (int j = 0; j < 16; j++) {
        const int jn = (j + 1) & 15;    // wrap-around prefetch: uniform wait counts
        CP_WAIT(1);                     // K_j (and Q on j=0) arrived; V_j may fly
        __syncthreads();

        // ---- S = Q x K^T (64 x 128, K=64), bf16x3, log2-domain ----
        float sacc[4][4] = {};
        #pragma unroll
        for (int ks = 0; ks < 4; ks++) {
            uint32_t qh_[4], ql_[4], kbh[2][4], kbl[2][4];
            lda_frag1(SB + OQ + ks * 4096, wm, lane, qh_, ql_);
            ldb_frag(SB + OK_ + ks * 8192, wn, lane, kbh, kbl);
            #pragma unroll
            for (int ni = 0; ni < 4; ni++) {
                const int g = ni >> 1, o = (ni & 1) << 1;
                MMA16816(sacc[ni], qh_, kbh[g][o], kbh[g][o + 1]);
                MMA16816(sacc[ni], qh_, kbl[g][o], kbl[g][o + 1]);
                MMA16816(sacc[ni], ql_, kbh[g][o], kbh[g][o + 1]);
            }
        }
        __syncthreads();                // K_j consumed
        issue_tile<128, 4, 512>(SB + OK_, Kh + (size_t)jn * 128 * EMB,
                                Kl + (size_t)jn * 128 * EMB, EMB);
        CP_COMMIT();                    // group [K_{j+1}]

        // ---- convert: |s| -> l1, exp2 -> P hi/lo smem + row sums ----
        {
            const int r0 = wm + (lane >> 2);
            const int r1 = r0 + 8;
            float rs0 = 0.0f, rs1 = 0.0f;
            #pragma unroll
            for (int ni = 0; ni < 4; ni++) {
                const int c  = wn + ni * 8 + ((lane & 3) << 1);
                const int st = c >> 4, kk = c & 15;
                const int ch = kk >> 3, intra = (kk & 7) * 2;
                float s0 = sacc[ni][0], s1 = sacc[ni][1];
                float s2 = sacc[ni][2], s3 = sacc[ni][3];
                l1acc += fabsf(s0) + fabsf(s1) + fabsf(s2) + fabsf(s3);
                float p0 = ex2(s0), p1 = ex2(s1);
                float p2 = ex2(s2), p3 = ex2(s3);
                rs0 += p0 + p1; rs1 += p2 + p3;
                __nv_bfloat16 H0, L0, H1, L1;
                cvt_hl(p0, H0, L0); cvt_hl(p1, H1, L1);
                const uint32_t b0 = OP + st * 4096 + r0 * 64;
                *(uint32_t*)(SM + b0 + (((ch)     ^ ((r0 >> 1) & 3)) << 4) + intra) = pack2(H0, H1);
                *(uint32_t*)(SM + b0 + (((ch + 2) ^ ((r0 >> 1) & 3)) << 4) + intra) = pack2(L0, L1);
                cvt_hl(p2, H0, L0); cvt_hl(p3, H1, L1);
                const uint32_t b1 = OP + st * 4096 + r1 * 64;
                *(uint32_t*)(SM + b1 + (((ch)     ^ ((r1 >> 1) & 3)) << 4) + intra) = pack2(H0, H1);
                *(uint32_t*)(SM + b1 + (((ch + 2) ^ ((r1 >> 1) & 3)) << 4) + intra) = pack2(L0, L1);
            }
            rs0 += __shfl_xor_sync(0xffffffffu, rs0, 1);
            rs0 += __shfl_xor_sync(0xffffffffu, rs0, 2);
            rs1 += __shfl_xor_sync(0xffffffffu, rs1, 1);
            rs1 += __shfl_xor_sync(0xffffffffu, rs1, 2);
            if ((lane & 3) == 0) {
                atomicAdd(&slf[r0], rs0);
                atomicAdd(&slf[r1], rs1);
            }
        }

        CP_WAIT(1);                     // V_j arrived (K_{j+1} still flying)
        __syncthreads();                // publish P_j + slf

        // ---- PV combined: O0 += P x V0^T, O1 += P x V1^T ----
        #pragma unroll
        for (int ks = 0; ks < 8; ks++) {
            uint32_t ph[4], pl[4];
            lda_frag1(SB + OP + ks * 4096, wm, lane, ph, pl);
            uint32_t v0h[2][4], v0l[2][4], v1h[2][4], v1l[2][4];
            ldb_frag(SB + OV0 + ks * 8192, wn, lane, v0h, v0l);
            ldb_frag(SB + OV1 + ks * 8192, wn, lane, v1h, v1l);
            #pragma unroll
            for (int ni = 0; ni < 4; ni++) {
                const int g = ni >> 1, o = (ni & 1) << 1;
                MMA16816(oacc0[ni], ph, v0h[g][o], v0h[g][o + 1]);
                MMA16816(oacc0[ni], ph, v0l[g][o], v0l[g][o + 1]);
                MMA16816(oacc0[ni], pl, v0h[g][o], v0h[g][o + 1]);
                MMA16816(oacc1[ni], ph, v1h[g][o], v1h[g][o + 1]);
                MMA16816(oacc1[ni], ph, v1l[g][o], v1l[g][o + 1]);
                MMA16816(oacc1[ni], pl, v1h[g][o], v1h[g][o + 1]);
            }
        }
        __syncthreads();                // V_j consumed
        issue_tile<128, 8, 512>(SB + OV0, Vh0 + jn * 128, Vl0 + jn * 128, SEQ);
        issue_tile<128, 8, 512>(SB + OV1, Vh1 + jn * 128, Vl1 + jn * 128, SEQ);
        CP_COMMIT();                    // group [V_{j+1}]
    }

    CP_WAIT(0);
    __syncthreads();

    // ---- epilogue: O / l -> feat hi/lo ----
    {
        const int r0 = wm + (lane >> 2);
        const float inv0 = 1.0f / slf[r0];
        const float inv1 = 1.0f / slf[r0 + 8];
        #pragma unroll
        for (int hv = 0; hv < 2; hv++) {
            #pragma unroll
            for (int ni = 0; ni < 4; ni++) {
                const float* a = hv ? oacc1[ni] : oacc0[ni];
                const int c = hv * 128 + wn + ni * 8 + ((lane & 3) << 1);
                const size_t d0 = ((size_t)b * SEQ + qbase + r0) * HFB + h * FB + c;
                const size_t d1 = ((size_t)b * SEQ + qbase + r0 + 8) * HFB + h * FB + c;
                float v0 = a[0] * inv0, v1 = a[1] * inv0;
                float v2 = a[2] * inv1, v3 = a[3] * inv1;
                __nv_bfloat16 H0, L0, H1, L1;
                cvt_hl(v0, H0, L0); cvt_hl(v1, H1, L1);
                *(uint32_t*)(g_fh + d0) = pack2(H0, H1);
                *(uint32_t*)(g_fl + d0) = pack2(L0, L1);
                cvt_hl(v2, H0, L0); cvt_hl(v3, H1, L1);
                *(uint32_t*)(g_fh + d1) = pack2(H0, H1);
                *(uint32_t*)(g_fl + d1) = pack2(L0, L1);
            }
        }
    }

    // ---- l1 reduction (log2-domain sums, scaled by ln2) ----
    #pragma unroll
    for (int o = 16; o > 0; o >>= 1)
        l1acc += __shfl_xor_sync(0xffffffffu, l1acc, o);
    if (lane == 0) red[wid] = l1acc;
    __syncthreads();
    if (tid == 0) {
        float t = 0.0f;
        #pragma unroll
        for (int w = 0; w < 16; w++) t += red[w];
        atomicAdd(&l1[b], t * L1SCALE);
    }
}

// ---------------- tiny init --------------------------------------------------
__global__ void zero_l1_kernel(float* l1) {
    if (threadIdx.x < BATCH) l1[threadIdx.x] = 0.0f;
}

// ---------------- conv: z_b and W_c -> bf16 hi/lo ----------------------------
__global__ __launch_bounds__(256) void conv_kernel(const float* __restrict__ zb,
                                                   const float* __restrict__ Wc)
{
    const int NZ = BATCH * FB * SEQ / 4;
    const int NW = FA * HFB / 4;
    int i = blockIdx.x * 256 + threadIdx.x;
    if (i < NZ) {
        float4 v = ((const float4*)zb)[i];
        __nv_bfloat16 h0,l0,h1,l1,h2,l2,h3,l3;
        cvt_hl(v.x,h0,l0); cvt_hl(v.y,h1,l1); cvt_hl(v.z,h2,l2); cvt_hl(v.w,h3,l3);
        ((uint2*)g_vh)[i] = make_uint2(pack2(h0,h1), pack2(h2,h3));
        ((uint2*)g_vl)[i] = make_uint2(pack2(l0,l1), pack2(l2,l3));
    } else if (i < NZ + NW) {
        int j = i - NZ;
        float4 v = ((const float4*)Wc)[j];
        __nv_bfloat16 h0,l0,h1,l1,h2,l2,h3,l3;
        cvt_hl(v.x,h0,l0); cvt_hl(v.y,h1,l1); cvt_hl(v.z,h2,l2); cvt_hl(v.w,h3,l3);
        ((uint2*)g_wh)[j] = make_uint2(pack2(h0,h1), pack2(h2,h3));
        ((uint2*)g_wl)[j] = make_uint2(pack2(l0,l1), pack2(l2,l3));
    }
}

// ---------------- embed: fp32 SIMT GEMM, epilogue -> qT/kT bf16 hi/lo --------
// q path is pre-scaled by QSCALE (softmax scale folded into log2 domain)
#define BM 128
#define BN 128
#define BK 8
#define TM 8
#define TN 8
__global__ __launch_bounds__(256) void embed_kernel(
    const float* __restrict__ Wa, const float* __restrict__ za,
    const float* __restrict__ Wb, const float* __restrict__ zb)
{
    const int bz = blockIdx.z;
    const int b = bz >> 1, sel = bz & 1;
    const float* __restrict__ A  = sel ? Wb : Wa;                       // [512 x 256]
    const float* __restrict__ Bm = (sel ? zb : za) + (size_t)b*FA*SEQ;  // [256 x 2048]
    __nv_bfloat16* __restrict__ Oh = sel ? g_kh : g_qh;
    __nv_bfloat16* __restrict__ Ol = sel ? g_kl : g_ql;
    const float scl = sel ? 1.0f : QSCALE;

    __shared__ float As[BK][BM];
    __shared__ float Bs[BK][BN];

    const int tid = threadIdx.x;
    const int m0 = blockIdx.y * BM;
    const int n0 = blockIdx.x * BN;
    const int K = FA;
    const int ty = tid >> 4, tx = tid & 15;

    float acc[TM][TN] = {};

    for (int k0 = 0; k0 < K; k0 += BK) {
        {
            const int mm = tid >> 1, kk = (tid & 1) * 4;
            float4 v = *(const float4*)&A[(size_t)(m0 + mm) * K + k0 + kk];
            As[kk + 0][mm] = v.x; As[kk + 1][mm] = v.y;
            As[kk + 2][mm] = v.z; As[kk + 3][mm] = v.w;
        }
        {
            const int kk = tid >> 5, nn = (tid & 31) * 4;
            *(float4*)&Bs[kk][nn] = *(const float4*)&Bm[(size_t)(k0 + kk) * SEQ + n0 + nn];
        }
        __syncthreads();
        #pragma unroll
        for (int kk = 0; kk < BK; kk++) {
            float a[TM], bb[TN];
            *(float4*)&a[0]  = *(const float4*)&As[kk][ty * TM];
            *(float4*)&a[4]  = *(const float4*)&As[kk][ty * TM + 4];
            *(float4*)&bb[0] = *(const float4*)&Bs[kk][tx * TN];
            *(float4*)&bb[4] = *(const float4*)&Bs[kk][tx * TN + 4];
            #pragma unroll
            for (int i = 0; i < TM; i++)
                #pragma unroll
                for (int j = 0; j < TN; j++)
                    acc[i][j] += a[i] * bb[j];
        }
        __syncthreads();
    }
    // transposed epilogue: m = o = h*64+e -> write [bh][n][e]
    const int mbase = m0 + ty * TM;
    const int h = mbase >> 6, e0 = mbase & 63;
    const size_t bh = (size_t)(b * NHEADS + h);
    #pragma unroll
    for (int j = 0; j < TN; j++) {
        const int n = n0 + tx * TN + j;
        uint32_t hw[4], lw[4];
        #pragma unroll
        for (int p = 0; p < 4; p++) {
            __nv_bfloat16 ha, la, hb, lb;
            cvt_hl(acc[2*p][j] * scl, ha, la);
            cvt_hl(acc[2*p+1][j] * scl, hb, lb);
            hw[p] = pack2(ha, hb); lw[p] = pack2(la, lb);
        }
        const size_t dst = (bh * SEQ + n) * EMB + e0;
        *(uint4*)(Oh + dst) = make_uint4(hw[0], hw[1], hw[2], hw[3]);
        *(uint4*)(Ol + dst) = make_uint4(lw[0], lw[1], lw[2], lw[3]);
    }
}

// ---------------- out: mma.sync bf16x3, K=2048, fp32 out ---------------------
#define ISSUE_STAGE(st, k0)                                                     \
    do {                                                                        \
        _Pragma("unroll")                                                       \
        for (int p = 0; p < 4; p++) {                                           \
            int id = tid + (p << 8);                                            \
            int isB = id >> 9;                                                  \
            int rem = id & 511;                                                 \
            int r = rem >> 2, cc = rem & 3;                                     \
            const __nv_bfloat16* src =                                          \
                (isB ? (cc < 2 ? Bh : Bl) : (cc < 2 ? Ah : Al))                 \
                + (size_t)r * (isB ? ldb : lda) + (k0) + ((cc & 1) << 3);       \
            uint32_t dst = sb + (st) * 16384 + isB * 8192 + r * 64              \
                         + ((cc ^ ((r >> 1) & 3)) << 4);                        \
            CP_ASYNC16(dst, src);                                               \
        }                                                                       \
    } while (0)

__device__ __forceinline__ void mma_nt_128(
    const __nv_bfloat16* __restrict__ Ah, const __nv_bfloat16* __restrict__ Al, int lda,
    const __nv_bfloat16* __restrict__ Bh, const __nv_bfloat16* __restrict__ Bl, int ldb,
    int K, float acc[4][4][4], unsigned char* sbuf)
{
    const int tid  = threadIdx.x;
    const int lane = tid & 31;
    const int wid  = tid >> 5;
    const int wm   = (wid >> 2) * 64;
    const int wn   = (wid & 3) * 32;
    const uint32_t sb = smem_u32(sbuf);

    #pragma unroll
    for (int mi = 0; mi < 4; mi++)
        #pragma unroll
        for (int ni = 0; ni < 4; ni++)
            #pragma unroll
            for (int q = 0; q < 4; q++) acc[mi][ni][q] = 0.0f;

    const int nst = K >> 4;
    ISSUE_STAGE(0, 0);
    CP_COMMIT();

    for (int s = 0; s < nst; s++) {
        if (s + 1 < nst) {
            ISSUE_STAGE((s + 1) & 1, (s + 1) << 4);
            CP_COMMIT();
            CP_WAIT(1);
        } else {
            CP_WAIT(0);
        }
        __syncthreads();

        const uint32_t stb = sb + (uint32_t)(s & 1) * 16384;
        uint32_t ah[4][4], al[4][4], bhf[2][4], blf[2][4];
        #pragma unroll
        for (int mi = 0; mi < 4; mi++) {
            int r  = wm + mi * 16 + (lane & 15);
            int ch = (lane >> 4) & 1;
            uint32_t rb = stb + r * 64;
            LDSM4(ah[mi], rb + (((ch)     ^ ((r >> 1) & 3)) << 4));
            LDSM4(al[mi], rb + (((ch + 2) ^ ((r >> 1) & 3)) << 4));
        }
        #pragma unroll
        for (int nb = 0; nb < 2; nb++) {
            int r  = wn + nb * 16 + (lane & 7) + ((lane & 16) ? 8 : 0);
            int ch = (lane >> 3) & 1;
            uint32_t rb = stb + 8192 + r * 64;
            LDSM4(bhf[nb], rb + (((ch)     ^ ((r >> 1) & 3)) << 4));
            LDSM4(blf[nb], rb + (((ch + 2) ^ ((r >> 1) & 3)) << 4));
        }
        #pragma unroll
        for (int mi = 0; mi < 4; mi++)
            #pragma unroll
            for (int ni = 0; ni < 4; ni++) {
                const int g = ni >> 1, o = (ni & 1) << 1;
                MMA16816(acc[mi][ni], ah[mi], bhf[g][o], bhf[g][o + 1]);
                MMA16816(acc[mi][ni], ah[mi], blf[g][o], blf[g][o + 1]);
                MMA16816(acc[mi][ni], al[mi], bhf[g][o], bhf[g][o + 1]);
            }
        __syncthreads();
    }
}

__global__ __launch_bounds__(256) void out_mma_kernel(float* __restrict__ out)
{
    __shared__ __align__(16) unsigned char sbuf[2][16384];
    const int tid = threadIdx.x, lane = tid & 31, wid = tid >> 5;
    const int b = blockIdx.z;
    const int m0 = blockIdx.y * 128;
    const int n0 = blockIdx.x * 128;

    const __nv_bfloat16* Ah = g_fh + ((size_t)b * SEQ + m0) * HFB;
    const __nv_bfloat16* Al = g_fl + ((size_t)b * SEQ + m0) * HFB;
    const __nv_bfloat16* Bh = g_wh + (size_t)n0 * HFB;
    const __nv_bfloat16* Bl = g_wl + (size_t)n0 * HFB;

    float acc[4][4][4];
    mma_nt_128(Ah, Al, HFB, Bh, Bl, HFB, HFB, acc, &sbuf[0][0]);

    const int wm = (wid >> 2) * 64, wn = (wid & 3) * 32;
    #pragma unroll
    for (int mi = 0; mi < 4; mi++) {
        #pragma unroll
        for (int ni = 0; ni < 4; ni++) {
            const int r0 = m0 + wm + mi * 16 + (lane >> 2);
            const int c  = n0 + wn + ni * 8 + ((lane & 3) << 1);
            *(float2*)(out + ((size_t)b * SEQ + r0) * FA + c) =
                make_float2(acc[mi][ni][0], acc[mi][ni][1]);
            *(float2*)(out + ((size_t)b * SEQ + r0 + 8) * FA + c) =
                make_float2(acc[mi][ni][2], acc[mi][ni][3]);
        }
    }
}

// ---------------- launch -----------------------------------------------------
extern "C" void kernel_launch(void* const* d_in, const int* in_sizes, int n_in,
                              void* d_out, int out_size)
{
    const float* z_a = (const float*)d_in[0];   // [2, 256, 2048]
    const float* z_b = (const float*)d_in[1];   // [2, 256, 2048]
    const float* W_a = (const float*)d_in[2];   // [512, 256]
    const float* W_b = (const float*)d_in[3];   // [512, 256]
    const float* W_c = (const float*)d_in[4];   // [256, 2048]
    float* out = (float*)d_out;                 // [2, 2048, 256] then l1 [2]
    float* l1  = out + (size_t)BATCH * SEQ * FA;

    cudaFuncSetAttribute(attn_fused_kernel,
                         cudaFuncAttributeMaxDynamicSharedMemorySize, SMEM_FUSED);

    zero_l1_kernel<<<1, 32>>>(l1);

    {
        const int nchunks = (BATCH * FB * SEQ + FA * HFB) / 4;
        conv_kernel<<<(nchunks + 255) / 256, 256>>>(z_b, W_c);
    }
    {
        dim3 grid(SEQ / BN, (NHEADS * EMB) / BM, BATCH * 2);
        embed_kernel<<<grid, 256>>>(W_a, z_a, W_b, z_b);
    }
    {
        dim3 grid(SEQ / 64, BATCH * NHEADS);
        attn_fused_kernel<<<grid, 512, SMEM_FUSED>>>(l1);
    }
    {
        dim3 grid(FA / 128, SEQ / 128, BATCH);
        out_mma_kernel<<<grid, 256>>>(out);
    }
}